// round 1
// baseline (speedup 1.0000x reference)
#include <cuda_runtime.h>

#define BATCH 131072
#define NCH 16
#define NK 15
#define NZ 256
#define NCOUT 10
#define MAXREG 128

// ---------------- scratch (device globals; no allocation) ----------------
__device__ unsigned       g_seen[NCH][1024];            // 32768-bit set per channel
__device__ unsigned short g_mask[BATCH * NCH];          // per-element per-channel sign mask
__device__ int            g_cnt[NCH];                   // #distinct masks per channel (<=121)
__device__ unsigned short g_maskOfRegion[NCH][MAXREG];  // region id -> mask
__device__ short          g_regionMap[NCH][32768];      // mask -> region id (only observed entries valid)
__device__ float          g_zreg[NCH][MAXREG][NZ];      // per-region half z-row
__device__ unsigned char  g_cross[8][MAXREG][MAXREG];   // argmax index per (c8, rA, rB)

// ---------------- P0: zero the observation bitsets ----------------
__global__ void k_zero_seen() {
    g_seen[blockIdx.x][threadIdx.x] = 0u;
}

// ---------------- P1: per-element sign masks + observation ----------------
__global__ void k_masks(const int* __restrict__ x,
                        const float* __restrict__ lenLUT,
                        const float* __restrict__ ipdLUT,
                        const float* __restrict__ S,
                        const float* __restrict__ T) {
    __shared__ float sS[NCH * 2 * NK];
    __shared__ float sT[NCH * NK];
    for (int i = threadIdx.x; i < NCH * 2 * NK; i += blockDim.x) sS[i] = S[i];
    for (int i = threadIdx.x; i < NCH * NK; i += blockDim.x) sT[i] = T[i];
    __syncthreads();

    int b = blockIdx.x * blockDim.x + threadIdx.x;
    const int2*   xp = (const int2*)x + (size_t)b * NCH;
    const float2* Lt = (const float2*)lenLUT;
    const float2* It = (const float2*)ipdLUT;

    #pragma unroll
    for (int c = 0; c < NCH; c++) {
        int2   xv = xp[c];
        float2 l  = __ldg(&Lt[xv.x]);
        float2 p  = __ldg(&It[xv.y]);
        float  e0 = l.x + p.x;
        float  e1 = l.y + p.y;
        unsigned m = 0;
        #pragma unroll
        for (int k = 0; k < NK; k++) {
            float dot = fmaf(e1, sS[(c * 2 + 1) * NK + k], e0 * sS[(c * 2) * NK + k]);
            float y   = (dot - sT[c * NK + k]) - 1e-4f;
            m |= (__float_as_uint(y) >> 31) << k;   // bit set <=> y < 0 <=> sign = -1
        }
        g_mask[b * NCH + c] = (unsigned short)m;
        unsigned word = m >> 5, bit = 1u << (m & 31);
        if (!(g_seen[c][word] & bit)) atomicOr(&g_seen[c][word], bit);  // idempotent; stale read ok
    }
}

// ---------------- P2: deterministic dedup via block scan ----------------
__global__ void k_dedup() {   // <<<16, 1024>>>  one block per channel
    int c = blockIdx.x;
    int t = threadIdx.x;
    unsigned w  = g_seen[c][t];
    int      pc = __popc(w);
    __shared__ int sc[1024];
    sc[t] = pc;
    __syncthreads();
    for (int off = 1; off < 1024; off <<= 1) {   // Hillis-Steele inclusive scan
        int v = (t >= off) ? sc[t - off] : 0;
        __syncthreads();
        sc[t] += v;
        __syncthreads();
    }
    int id = sc[t] - pc;                          // exclusive prefix
    if (t == 1023) g_cnt[c] = min(sc[t], MAXREG); // geometry guarantees <=121
    unsigned ww = w;
    while (ww) {
        int bbit = __ffs(ww) - 1;
        ww &= ww - 1;
        unsigned mask = ((unsigned)t << 5) | (unsigned)bbit;
        if (id < MAXREG) {
            g_regionMap[c][mask]    = (short)id;
            g_maskOfRegion[c][id]   = (unsigned short)mask;
        }
        id++;
    }
}

// ---------------- P3: half z-rows per (channel, region) ----------------
__global__ void k_zreg(const float* __restrict__ H) {  // <<<16*128, 256>>>
    int c = blockIdx.x >> 7;
    int r = blockIdx.x & 127;
    if (r >= g_cnt[c]) return;
    unsigned m    = g_maskOfRegion[c][r];
    int      base = (c & 1) * NK;   // even channel -> H rows 0..14, odd -> 15..29
    int      k    = threadIdx.x;
    float acc = 0.f;
    #pragma unroll
    for (int d = 0; d < NK; d++) {
        float h = H[(base + d) * NZ + k];
        acc += ((m >> d) & 1) ? -h : h;
    }
    g_zreg[c][r][k] = acc;
}

// ---------------- P4: argmax table per (c8, rA, rB) ----------------
__global__ void k_cross() {   // <<<dim3(128, 8), 256>>>
    int c8 = blockIdx.y;
    int rA = blockIdx.x;
    int cA = 2 * c8, cB = 2 * c8 + 1;
    if (rA >= g_cnt[cA]) return;
    __shared__ float zA[NZ];
    zA[threadIdx.x] = g_zreg[cA][rA][threadIdx.x];
    __syncthreads();
    int nB   = g_cnt[cB];
    int warp = threadIdx.x >> 5;
    int lane = threadIdx.x & 31;
    for (int rB = warp; rB < nB; rB += 8) {
        const float* zb = g_zreg[cB][rB];
        float best = -__int_as_float(0x7f800000); // -inf
        int   bk   = 0;
        #pragma unroll
        for (int j = 0; j < 8; j++) {
            int   k = j * 32 + lane;              // ascending per lane -> strict '>' keeps first max
            float v = zA[k] + zb[k];
            if (v > best) { best = v; bk = k; }
        }
        #pragma unroll
        for (int off = 16; off; off >>= 1) {      // first-index-wins warp argmax
            float ov = __shfl_down_sync(0xffffffffu, best, off);
            int   ok = __shfl_down_sync(0xffffffffu, bk, off);
            if (ov > best || (ov == best && ok < bk)) { best = ov; bk = ok; }
        }
        if (lane == 0) g_cross[c8][rA][rB] = (unsigned char)bk;
    }
}

// ---------------- M: per-element gather + log_softmax ----------------
__global__ void k_main(const float* __restrict__ LUT, float* __restrict__ out) {
    int b = blockIdx.x * blockDim.x + threadIdx.x;

    const uint4* mp = (const uint4*)(g_mask + (size_t)b * NCH);
    uint4 m0 = mp[0], m1 = mp[1];
    unsigned mw[8] = {m0.x, m0.y, m0.z, m0.w, m1.x, m1.y, m1.z, m1.w};

    int r[NCH];
    #pragma unroll
    for (int i = 0; i < 8; i++) {
        r[2 * i]     = g_regionMap[2 * i][mw[i] & 0xffffu];
        r[2 * i + 1] = g_regionMap[2 * i + 1][mw[i] >> 16];
    }

    float acc[NCOUT];
    #pragma unroll
    for (int j = 0; j < NCOUT; j++) acc[j] = 0.f;

    #pragma unroll
    for (int c8 = 0; c8 < 8; c8++) {
        int idx = g_cross[c8][r[2 * c8]][r[2 * c8 + 1]];
        const float2* p = (const float2*)(LUT + ((size_t)(c8 * 256 + idx)) * NCOUT);
        #pragma unroll
        for (int j = 0; j < 5; j++) {
            float2 v = __ldg(&p[j]);
            acc[2 * j]     += v.x;
            acc[2 * j + 1] += v.y;
        }
    }

    float mx = acc[0];
    #pragma unroll
    for (int j = 1; j < NCOUT; j++) mx = fmaxf(mx, acc[j]);
    float s = 0.f;
    #pragma unroll
    for (int j = 0; j < NCOUT; j++) s += expf(acc[j] - mx);
    float lg = logf(s);

    float2* op = (float2*)(out + (size_t)b * NCOUT);
    #pragma unroll
    for (int j = 0; j < 5; j++)
        op[j] = make_float2((acc[2 * j] - mx) - lg, (acc[2 * j + 1] - mx) - lg);
}

// ---------------- launch ----------------
extern "C" void kernel_launch(void* const* d_in, const int* in_sizes, int n_in,
                              void* d_out, int out_size) {
    const int*   x      = (const int*)d_in[0];
    const float* lenLUT = (const float*)d_in[1];
    const float* ipdLUT = (const float*)d_in[2];
    const float* S      = (const float*)d_in[3];
    const float* H      = (const float*)d_in[4];
    const float* T      = (const float*)d_in[5];
    const float* LUT    = (const float*)d_in[6];
    float*       out    = (float*)d_out;

    k_zero_seen<<<16, 1024>>>();
    k_masks<<<BATCH / 128, 128>>>(x, lenLUT, ipdLUT, S, T);
    k_dedup<<<16, 1024>>>();
    k_zreg<<<NCH * MAXREG, 256>>>(H);
    k_cross<<<dim3(MAXREG, 8), 256>>>();
    k_main<<<BATCH / 256, 256>>>(LUT, out);
}